// round 10
// baseline (speedup 1.0000x reference)
#include <cuda_runtime.h>
#include <math.h>

#define N_NODES 15
#define EMBED   2048
#define F1      1024
#define F2      512
#define NE      120
#define H1N     480
#define H2N     1920
#define HN      (N_NODES*EMBED)   // 30720

// ---------- scratch (device globals; zero-init at load, reset at kernel end) ----------
__device__ float g_h2[H2N];
__device__ float g_H[HN];
__device__ float g_HW1[N_NODES*F1];
__device__ float g_X1[N_NODES*F1];
__device__ float g_HW2[N_NODES*F2];
__device__ float g_X2[N_NODES*F2];
__device__ float g_m[F2];
__device__ float g_ctx[F2];
__device__ int   g_cnt1[8], g_cnt2[4];
__device__ int   g_done1, g_done2, g_done3;
__device__ int   g_flag1, g_flag2, g_flag3;
__device__ int   g_pre, g_flag0;       // phase A grid barrier
__device__ int   g_tile;               // work-stealing counter for W3 tiles
__device__ int   g_bdone;              // blocks finished with W3 phase

__device__ __forceinline__ void spin_flag(int* flag, int t) {
    if (t == 0) { while (atomicAdd(flag, 0) == 0) __nanosleep(64); }
    __syncthreads();
    __threadfence();
}

// =====================================================================
// GCN GEMM slice + last-block aggregation (unchanged from R8/R9 passing)
// =====================================================================
template <int L>
__device__ __forceinline__ void gcn_phase(int x, int y, int t,
                                          const float* __restrict__ W,
                                          const float* __restrict__ bias,
                                          const int* __restrict__ eidx) {
    constexpr int K  = (L == 0) ? 2048 : 1024;
    constexpr int N  = (L == 0) ? 1024 : 512;
    constexpr int NY = (L == 0) ? 16 : 8;
    const float* X  = (L == 0) ? g_H  : g_X1;
    float* OUT      = (L == 0) ? g_HW1 : g_HW2;
    float* XO       = (L == 0) ? g_X1 : g_X2;
    int*   cnt      = (L == 0) ? g_cnt1 : g_cnt2;
    int*   done     = (L == 0) ? &g_done1 : &g_done2;
    int*   flag     = (L == 0) ? &g_flag1 : &g_flag2;
    constexpr int NTILE = (L == 0) ? 8 : 4;

    __shared__ float4 Xt4[N_NODES * 32];
    float* Xt = (float*)Xt4;
    int k0 = y * 128;
    for (int idx = t; idx < N_NODES * 32; idx += 256) {
        int i = idx >> 5, c = idx & 31;
        Xt4[idx] = *(const float4*)(X + (size_t)i * K + k0 + 4 * c);
    }
    __syncthreads();

    int g  = t >> 7;
    int jt = t & 127;
    int j  = x * 128 + jt;
    const float* wp = W + (size_t)(k0 + g * 64) * N + j;
    float acc[N_NODES];
#pragma unroll
    for (int i = 0; i < N_NODES; i++) acc[i] = 0.f;
    for (int kb = 0; kb < 64; kb += 8) {
        float wv[8];
#pragma unroll
        for (int u = 0; u < 8; u++) wv[u] = __ldg(wp + (size_t)(kb + u) * N);
#pragma unroll
        for (int u = 0; u < 8; u++) {
            const float* xr = &Xt[g * 64 + kb + u];
#pragma unroll
            for (int i = 0; i < N_NODES; i++) acc[i] += xr[i * 128] * wv[u];
        }
    }
    __syncthreads();
    if (g == 1) {
#pragma unroll
        for (int i = 0; i < N_NODES; i++) Xt[i * 128 + jt] = acc[i];
    }
    __syncthreads();
    if (g == 0) {
#pragma unroll
        for (int i = 0; i < N_NODES; i++)
            atomicAdd(&OUT[i * N + j], acc[i] + Xt[i * 128 + jt]);
    }

    __threadfence();
    __syncthreads();
    __shared__ int isLast;
    if (t == 0) isLast = (atomicAdd(&cnt[x], 1) == NY - 1);
    __syncthreads();
    if (!isLast) return;

    __shared__ int   se[NE], de[NE];
    __shared__ float degs[N_NODES], dinv[N_NODES], nrm[NE];
    __shared__ float hws[N_NODES][128];
    __shared__ float outs[N_NODES][128];
    if (t < NE) { se[t] = eidx[t]; de[t] = eidx[NE + t]; }
    if (t < N_NODES) degs[t] = 1.f;
    __syncthreads();
    if (t < NE) atomicAdd(&degs[de[t]], 1.f);
    __syncthreads();
    if (t < N_NODES) dinv[t] = rsqrtf(degs[t]);
    __syncthreads();
    if (t < NE) nrm[t] = dinv[se[t]] * dinv[de[t]];
    if (t < 128) {
#pragma unroll
        for (int i = 0; i < N_NODES; i++) hws[i][t] = __ldcg(&OUT[i * N + x * 128 + t]);
    }
    __syncthreads();
    if (t < 128) {
        int jj = x * 128 + t;
#pragma unroll
        for (int i = 0; i < N_NODES; i++) outs[i][t] = hws[i][t] * dinv[i] * dinv[i];
        for (int e = 0; e < NE; e++)
            outs[de[e]][t] += hws[se[e]][t] * nrm[e];

        float b = bias[jj];
        float s = 0.f;
#pragma unroll
        for (int i = 0; i < N_NODES; i++) {
            float v = outs[i][t] + b;
            if (L == 0) v = fmaxf(v, 0.f);
            XO[i * N + jj] = v;
            s += v;
        }
        if (L == 1) g_m[jj] = s * (1.f / 15.f);
    }
    __threadfence();
    __syncthreads();
    if (t == 0) {
        if (atomicAdd(done, 1) == NTILE - 1) atomicExch(flag, 1);
    }
}

// =====================================================================
// MEGAKERNEL: phase A (MLP1+MLP2+init) -> barrier ->
//             phase B (sparse W3 matvec, work-stealing) -> barrier ->
//             phase C (gcn0 -> gcn1 -> ctx -> final) -> reset state
// grid = 148 blocks x 256 threads, all co-resident (1 block/SM)
// =====================================================================
__global__ void __launch_bounds__(256) k_all(
    const float* __restrict__ f,   const float* __restrict__ W1, const float* __restrict__ b1,
    const float* __restrict__ W2,  const float* __restrict__ b2,
    const float4* __restrict__ W3v,const float* __restrict__ b3,
    const float* __restrict__ gW1, const float* __restrict__ gb1,
    const float* __restrict__ gW2, const float* __restrict__ gb2,
    const float* __restrict__ attW,
    const float* __restrict__ fcW, const float* __restrict__ fcb,
    const int* __restrict__ eidx,  const float* __restrict__ target,
    float* __restrict__ out) {
    int b = blockIdx.x, t = threadIdx.x;

    // ================= PHASE A =================
    if (b < 60) {
        __shared__ float sf[N_NODES];
        __shared__ float sh1[H1N];
        __shared__ float red[8][32];
        if (t < N_NODES) sf[t] = f[t];
        __syncthreads();
        for (int j = t; j < H1N; j += 256) {
            float wv[N_NODES];
#pragma unroll
            for (int i = 0; i < N_NODES; i++) wv[i] = __ldg(&W1[i * H1N + j]);
            float a = b1[j];
#pragma unroll
            for (int i = 0; i < N_NODES; i++) a += sf[i] * wv[i];
            sh1[j] = fmaxf(a, 0.f);
        }
        __syncthreads();
        int col = b * 32 + (t & 31);
        int s   = t >> 5;                 // 8-way k-split of K=480
        int k0  = s * 60;
        float a = 0.f;
#pragma unroll
        for (int kb = 0; kb < 60; kb += 20) {
            float wv[20];
#pragma unroll
            for (int u = 0; u < 20; u++) wv[u] = __ldg(&W2[(size_t)(k0 + kb + u) * H2N + col]);
#pragma unroll
            for (int u = 0; u < 20; u++) a += sh1[k0 + kb + u] * wv[u];
        }
        red[s][t & 31] = a;
        __syncthreads();
        if (t < 32) {
            float v = b2[col];
#pragma unroll
            for (int s2 = 0; s2 < 8; s2++) v += red[s2][t];
            g_h2[col] = fmaxf(v, 0.f);
        }
    } else {
        int gt = (b - 60) * 256 + t;      // 0 .. 22527
        const int GS = 88 * 256;
#pragma unroll 2
        for (int i = gt; i < HN; i += GS)  g_H[i]   = b3[i];
        if (gt < N_NODES * F1)             g_HW1[gt] = 0.f;
        if (gt < N_NODES * F2)             g_HW2[gt] = 0.f;
        if (gt < F2)                       g_ctx[gt] = 0.f;
    }

    // ---- grid barrier: h2 + all inits visible ----
    __threadfence();
    __syncthreads();
    if (t == 0) {
        if (atomicAdd(&g_pre, 1) == 147) atomicExch(&g_flag0, 1);
    }
    spin_flag(&g_flag0, t);

    // ================= PHASE B: sparse W3 matvec, work stealing =========
    {
        __shared__ float sval[128];
        __shared__ int   sidx[128];
        __shared__ int   scnt;
        __shared__ int   stile;
        for (;;) {
            if (t == 0) stile = atomicAdd(&g_tile, 1);
            __syncthreads();                    // also protects sval reuse
            int tile = stile;
            if (tile >= 480) break;
            int x = tile % 30;                  // 30 col-groups of 256 float4
            int y = tile / 30;                  // 16 k-segments of 120
            int k0 = y * 120;
            if (t == 0) scnt = 0;
            __syncthreads();
            if (t < 120) {
                float h = g_h2[k0 + t];
                if (h > 0.f) {
                    int p = atomicAdd(&scnt, 1);
                    sidx[p] = t; sval[p] = h;
                }
            }
            __syncthreads();
            int cnt = scnt;
            int pad = (cnt + 7) & ~7;
            if (t < 8 && cnt + t < pad) { sidx[cnt + t] = sidx[0]; sval[cnt + t] = 0.f; }
            __syncthreads();

            int c = x * 256 + t;                // 7680 float4 columns total
            const float4* base = W3v + (size_t)k0 * 7680 + c;
            float4 acc = make_float4(0.f, 0.f, 0.f, 0.f);
            for (int q = 0; q < cnt; q += 8) {
                int   id[8]; float hv[8]; float4 w[8];
#pragma unroll
                for (int u = 0; u < 8; u++) { id[u] = sidx[q + u]; hv[u] = sval[q + u]; }
#pragma unroll
                for (int u = 0; u < 8; u++) w[u] = __ldcs(base + (size_t)id[u] * 7680);
#pragma unroll
                for (int u = 0; u < 8; u++) {
                    acc.x += hv[u] * w[u].x; acc.y += hv[u] * w[u].y;
                    acc.z += hv[u] * w[u].z; acc.w += hv[u] * w[u].w;
                }
            }
            float* o = g_H + 4 * c;
            atomicAdd(o + 0, acc.x); atomicAdd(o + 1, acc.y);
            atomicAdd(o + 2, acc.z); atomicAdd(o + 3, acc.w);
        }
    }
    // ---- grid barrier: all W3 contributions landed ----
    __threadfence();
    __syncthreads();
    if (t == 0) atomicAdd(&g_bdone, 1);
    if (t == 0) { while (atomicAdd(&g_bdone, 0) < 148) __nanosleep(64); }
    __syncthreads();
    __threadfence();
    if (b >= 128) return;

    // ================= PHASE C: tail =================
    gcn_phase<0>(b & 7, b >> 3, t, gW1, gb1, eidx);
    if (b >= 32) return;

    spin_flag(&g_flag1, t);
    gcn_phase<1>(b & 3, b >> 2, t, gW2, gb2, eidx);

    spin_flag(&g_flag2, t);
    {
        __shared__ float sm[32];
        int k0 = (b >> 1) * 32;
        if (t < 32) sm[t] = g_m[k0 + t];
        __syncthreads();
        int j = (b & 1) * 256 + t;
        float a = 0.f;
        for (int kb = 0; kb < 32; kb += 8) {
            float wv[8];
#pragma unroll
            for (int u = 0; u < 8; u++) wv[u] = __ldg(&attW[(size_t)(k0 + kb + u) * F2 + j]);
#pragma unroll
            for (int u = 0; u < 8; u++) a += sm[kb + u] * wv[u];
        }
        atomicAdd(&g_ctx[j], a);
        __threadfence();
        __syncthreads();
        if (t == 0) {
            if (atomicAdd(&g_done3, 1) == 31) atomicExch(&g_flag3, 1);
        }
    }
    if (b != 0) return;

    spin_flag(&g_flag3, t);
    {
        __shared__ float ctx_s[F2];
        __shared__ float sc[N_NODES];
        __shared__ float lg[3];
        ctx_s[t]       = tanhf(g_ctx[t]);
        ctx_s[t + 256] = tanhf(g_ctx[t + 256]);
        if (t < 3) lg[t] = fcb[t];
        __syncthreads();

        int w = t >> 5, l = t & 31;
#pragma unroll
        for (int r = 0; r < 2; r++) {
            int n = w + 8 * r;
            if (n < N_NODES) {
                float v = 0.f;
#pragma unroll
                for (int q = 0; q < 16; q++) {
                    int j = l + 32 * q;
                    v += g_X2[n * F2 + j] * ctx_s[j];
                }
#pragma unroll
                for (int o = 16; o > 0; o >>= 1) v += __shfl_xor_sync(0xffffffffu, v, o);
                if (l == 0) sc[n] = 1.f / (1.f + expf(-v));
            }
        }
        __syncthreads();

        float p0 = 0.f, p1 = 0.f, p2 = 0.f;
#pragma unroll
        for (int r = 0; r < 2; r++) {
            int col = t + 256 * r;
            float rep = 0.f;
#pragma unroll
            for (int i = 0; i < N_NODES; i++) rep += g_X2[i * F2 + col] * sc[i];
            p0 += rep * fcW[col * 3 + 0];
            p1 += rep * fcW[col * 3 + 1];
            p2 += rep * fcW[col * 3 + 2];
        }
#pragma unroll
        for (int o = 16; o > 0; o >>= 1) {
            p0 += __shfl_xor_sync(0xffffffffu, p0, o);
            p1 += __shfl_xor_sync(0xffffffffu, p1, o);
            p2 += __shfl_xor_sync(0xffffffffu, p2, o);
        }
        if (l == 0) { atomicAdd(&lg[0], p0); atomicAdd(&lg[1], p1); atomicAdd(&lg[2], p2); }
        __syncthreads();

        if (t == 0) {
            float l0 = lg[0], l1 = lg[1], l2 = lg[2];
            float mx = fmaxf(l0, fmaxf(l1, l2));
            float e0 = expf(l0 - mx), e1 = expf(l1 - mx), e2 = expf(l2 - mx);
            float s = e0 + e1 + e2;
            float t0 = target[0], t1 = target[1], t2 = target[2];
            int cls = 0; float tm = t0;
            if (t1 > tm) { tm = t1; cls = 1; }
            if (t2 > tm) { tm = t2; cls = 2; }
            float lcls = (cls == 0) ? l0 : ((cls == 1) ? l1 : l2);
            out[0] = -(lcls - mx - logf(s));
            out[1] = e0 / s; out[2] = e1 / s; out[3] = e2 / s;

            // ---- reset all sync state for next replay (block 0 is last alive) ----
            g_pre = 0; g_flag0 = 0; g_tile = 0; g_bdone = 0;
            g_done1 = 0; g_done2 = 0; g_done3 = 0;
            g_flag1 = 0; g_flag2 = 0; g_flag3 = 0;
#pragma unroll
            for (int i = 0; i < 8; i++) g_cnt1[i] = 0;
#pragma unroll
            for (int i = 0; i < 4; i++) g_cnt2[i] = 0;
            __threadfence();
        }
    }
}

// ---------- host ----------
extern "C" void kernel_launch(void* const* d_in, const int* in_sizes, int n_in,
                              void* d_out, int out_size) {
    const float* f      = (const float*)d_in[0];
    const int*   eidx   = (const int*)  d_in[1];
    const float* target = (const float*)d_in[2];
    const float* W1     = (const float*)d_in[3];
    const float* b1     = (const float*)d_in[4];
    const float* W2     = (const float*)d_in[5];
    const float* b2     = (const float*)d_in[6];
    const float* W3     = (const float*)d_in[7];
    const float* b3     = (const float*)d_in[8];
    const float* gW1    = (const float*)d_in[9];
    const float* gb1    = (const float*)d_in[10];
    const float* gW2    = (const float*)d_in[11];
    const float* gb2    = (const float*)d_in[12];
    const float* attW   = (const float*)d_in[13];
    const float* fcW    = (const float*)d_in[14];
    const float* fcb    = (const float*)d_in[15];
    float* out = (float*)d_out;

    k_all<<<148, 256>>>(f, W1, b1, W2, b2, (const float4*)W3, b3,
                        gW1, gb1, gW2, gb2, attW, fcW, fcb, eidx, target, out);
}

// round 11
// speedup vs baseline: 1.2856x; 1.2856x over previous
#include <cuda_runtime.h>
#include <math.h>

#define N_NODES 15
#define EMBED   2048
#define F1      1024
#define F2      512
#define NE      120
#define H1N     480
#define H2N     1920
#define HN      (N_NODES*EMBED)   // 30720

// ---------- scratch (device globals) ----------
__device__ float g_h2[H2N];
__device__ float g_H[HN];
__device__ float g_HW1[N_NODES*F1];
__device__ float g_X1[N_NODES*F1];
__device__ float g_HW2[N_NODES*F2];
__device__ float g_X2[N_NODES*F2];
__device__ float g_m[F2];
__device__ float g_ctx[F2];
__device__ int   g_cnt1[8], g_cnt2[4];   // per-x-tile k-split arrival counters (count to 16)
__device__ int   g_done1, g_done2, g_done3;
__device__ int   g_flag1, g_flag2, g_flag3;

// =====================================================================
// K_PRE: blocks 0..119: MLP1 (redundant, smem) + MLP2 (16 cols x 16 kgrp)
//        blocks 120..147: accumulator inits + sync-state reset
// =====================================================================
__global__ void __launch_bounds__(256) k_pre(
    const float* __restrict__ f,  const float* __restrict__ W1, const float* __restrict__ b1,
    const float* __restrict__ W2, const float* __restrict__ b2, const float* __restrict__ b3) {
    int bx = blockIdx.x, t = threadIdx.x;
    if (bx < 120) {
        __shared__ float sf[N_NODES];
        __shared__ float sh1[H1N];
        __shared__ float red[16][16];
        if (t < N_NODES) sf[t] = f[t];
        __syncthreads();
        for (int j = t; j < H1N; j += 256) {
            float wv[N_NODES];
#pragma unroll
            for (int i = 0; i < N_NODES; i++) wv[i] = __ldg(&W1[i * H1N + j]);
            float a = b1[j];
#pragma unroll
            for (int i = 0; i < N_NODES; i++) a += sf[i] * wv[i];
            sh1[j] = fmaxf(a, 0.f);
        }
        __syncthreads();
        int col = bx * 16 + (t & 15);
        int kg  = t >> 4;                 // 16 k-groups of 30
        int k0  = kg * 30;
        float a = 0.f;
#pragma unroll
        for (int kb = 0; kb < 30; kb += 15) {
            float wv[15];
#pragma unroll
            for (int u = 0; u < 15; u++) wv[u] = __ldg(&W2[(size_t)(k0 + kb + u) * H2N + col]);
#pragma unroll
            for (int u = 0; u < 15; u++) a += sh1[k0 + kb + u] * wv[u];
        }
        red[kg][t & 15] = a;
        __syncthreads();
        if (t < 16) {
            int c = bx * 16 + t;
            float v = b2[c];
#pragma unroll
            for (int s2 = 0; s2 < 16; s2++) v += red[s2][t];
            g_h2[c] = fmaxf(v, 0.f);
        }
    } else {
        int gt = (bx - 120) * 256 + t;    // 0 .. 7167
        const int GS = 28 * 256;
#pragma unroll 5
        for (int i = gt; i < HN; i += GS)           g_H[i]   = b3[i];
#pragma unroll 3
        for (int i = gt; i < N_NODES * F1; i += GS) g_HW1[i] = 0.f;
#pragma unroll 2
        for (int i = gt; i < N_NODES * F2; i += GS) g_HW2[i] = 0.f;
        if (gt < F2) g_ctx[gt] = 0.f;
        if (gt < 8)  g_cnt1[gt] = 0;
        if (gt < 4)  g_cnt2[gt] = 0;
        if (gt == 0) { g_done1 = 0; g_done2 = 0; g_done3 = 0;
                       g_flag1 = 0; g_flag2 = 0; g_flag3 = 0; }
    }
}

// =====================================================================
// K_MLP3: g_H += relu(h2) @ W3, skipping zero rows (verbatim from R9)
// =====================================================================
__global__ void __launch_bounds__(128) k_mlp3(const float4* __restrict__ W3v) {
    __shared__ float sval[128];
    __shared__ int   sidx[128];
    __shared__ int   scnt;
    int t = threadIdx.x;
    int k0 = blockIdx.y * 120;
    if (t == 0) scnt = 0;
    __syncthreads();
    if (t < 120) {
        float h = g_h2[k0 + t];
        if (h > 0.f) {
            int p = atomicAdd(&scnt, 1);
            sidx[p] = t; sval[p] = h;
        }
    }
    __syncthreads();
    int cnt = scnt;
    int pad = (cnt + 7) & ~7;
    if (t < 8 && cnt + t < pad) {
        sidx[cnt + t] = sidx[0];
        sval[cnt + t] = 0.f;
    }
    __syncthreads();

    int c = blockIdx.x * 128 + t;
    const float4* base = W3v + (size_t)k0 * 7680 + c;
    float4 acc = make_float4(0.f, 0.f, 0.f, 0.f);
    for (int q = 0; q < cnt; q += 8) {
        int   id[8]; float hv[8]; float4 w[8];
#pragma unroll
        for (int u = 0; u < 8; u++) { id[u] = sidx[q + u]; hv[u] = sval[q + u]; }
#pragma unroll
        for (int u = 0; u < 8; u++) w[u] = __ldcs(base + (size_t)id[u] * 7680);
#pragma unroll
        for (int u = 0; u < 8; u++) {
            acc.x += hv[u] * w[u].x; acc.y += hv[u] * w[u].y;
            acc.z += hv[u] * w[u].z; acc.w += hv[u] * w[u].w;
        }
    }
    float* o = g_H + 4 * c;
    atomicAdd(o + 0, acc.x); atomicAdd(o + 1, acc.y);
    atomicAdd(o + 2, acc.z); atomicAdd(o + 3, acc.w);
}

// =====================================================================
// tail helpers
// =====================================================================
__device__ __forceinline__ void spin_flag(int* flag, int t) {
    if (t == 0) { while (atomicAdd(flag, 0) == 0) __nanosleep(64); }
    __syncthreads();
    __threadfence();
}

// GCN GEMM slice + last-block aggregation.
// L=0: KTILE=128 (128 blocks: 8 x-tiles x 16 ksplit), 64 loads/thr, 4 waves
// L=1: KTILE=64  (64 blocks:  4 x-tiles x 16 ksplit), 32 loads/thr, 2 waves
template <int L>
__device__ __forceinline__ void gcn_phase(int x, int y, int t,
                                          const float* __restrict__ W,
                                          const float* __restrict__ bias,
                                          const int* __restrict__ eidx) {
    constexpr int K     = (L == 0) ? 2048 : 1024;
    constexpr int N     = (L == 0) ? 1024 : 512;
    constexpr int KTILE = (L == 0) ? 128 : 64;
    constexpr int HALF  = KTILE / 2;
    constexpr int NY    = 16;
    constexpr int NTILE = (L == 0) ? 8 : 4;
    const float* X  = (L == 0) ? g_H  : g_X1;
    float* OUT      = (L == 0) ? g_HW1 : g_HW2;
    float* XO       = (L == 0) ? g_X1 : g_X2;
    int*   cnt      = (L == 0) ? g_cnt1 : g_cnt2;
    int*   done     = (L == 0) ? &g_done1 : &g_done2;
    int*   flag     = (L == 0) ? &g_flag1 : &g_flag2;

    __shared__ float4 Xt4[N_NODES * 32];      // row stride fixed at 32 float4 = 128 f
    float* Xt = (float*)Xt4;
    int k0 = y * KTILE;
    for (int idx = t; idx < N_NODES * (KTILE / 4); idx += 256) {
        int i = idx / (KTILE / 4), c = idx % (KTILE / 4);
        Xt4[i * 32 + c] = *(const float4*)(X + (size_t)i * K + k0 + 4 * c);
    }
    __syncthreads();

    int g  = t >> 7;
    int jt = t & 127;
    int j  = x * 128 + jt;
    const float* wp = W + (size_t)(k0 + g * HALF) * N + j;
    float acc[N_NODES];
#pragma unroll
    for (int i = 0; i < N_NODES; i++) acc[i] = 0.f;
#pragma unroll
    for (int kb = 0; kb < HALF; kb += 16) {
        float wv[16];
#pragma unroll
        for (int u = 0; u < 16; u++) wv[u] = __ldg(wp + (size_t)(kb + u) * N);
#pragma unroll
        for (int u = 0; u < 16; u++) {
            const float* xr = &Xt[g * HALF + kb + u];
#pragma unroll
            for (int i = 0; i < N_NODES; i++) acc[i] += xr[i * 128] * wv[u];
        }
    }
    __syncthreads();                       // Xt reads complete
    if (g == 1) {
#pragma unroll
        for (int i = 0; i < N_NODES; i++) Xt[i * 128 + jt] = acc[i];
    }
    __syncthreads();
    if (g == 0) {
#pragma unroll
        for (int i = 0; i < N_NODES; i++)
            atomicAdd(&OUT[i * N + j], acc[i] + Xt[i * 128 + jt]);
    }

    // ---- last k-split block for this x-tile aggregates ----
    __threadfence();
    __syncthreads();
    __shared__ int isLast;
    if (t == 0) isLast = (atomicAdd(&cnt[x], 1) == NY - 1);
    __syncthreads();
    if (!isLast) return;

    __shared__ int   se[NE], de[NE];
    __shared__ float degs[N_NODES], dinv[N_NODES], nrm[NE];
    __shared__ float hws[N_NODES][128];
    __shared__ float outs[N_NODES][128];
    if (t < NE) { se[t] = eidx[t]; de[t] = eidx[NE + t]; }
    if (t < N_NODES) degs[t] = 1.f;
    __syncthreads();
    if (t < NE) atomicAdd(&degs[de[t]], 1.f);
    __syncthreads();
    if (t < N_NODES) dinv[t] = rsqrtf(degs[t]);
    __syncthreads();
    if (t < NE) nrm[t] = dinv[se[t]] * dinv[de[t]];
    if (t < 128) {
#pragma unroll
        for (int i = 0; i < N_NODES; i++) hws[i][t] = __ldcg(&OUT[i * N + x * 128 + t]);
    }
    __syncthreads();
    if (t < 128) {
        int jj = x * 128 + t;
#pragma unroll
        for (int i = 0; i < N_NODES; i++) outs[i][t] = hws[i][t] * dinv[i] * dinv[i];
        for (int e = 0; e < NE; e++)
            outs[de[e]][t] += hws[se[e]][t] * nrm[e];

        float b = bias[jj];
        float s = 0.f;
#pragma unroll
        for (int i = 0; i < N_NODES; i++) {
            float v = outs[i][t] + b;
            if (L == 0) v = fmaxf(v, 0.f);
            XO[i * N + jj] = v;
            s += v;
        }
        if (L == 1) g_m[jj] = s * (1.f / 15.f);
    }
    __threadfence();
    __syncthreads();
    if (t == 0) {
        if (atomicAdd(done, 1) == NTILE - 1) atomicExch(flag, 1);
    }
}

// =====================================================================
// K_TAIL: persistent fused gcn0 -> gcn1 -> ctx -> final
// grid = 128 blocks x 256 threads (all co-resident)
// =====================================================================
__global__ void __launch_bounds__(256) k_tail(
    const float* __restrict__ gW1, const float* __restrict__ gb1,
    const float* __restrict__ gW2, const float* __restrict__ gb2,
    const float* __restrict__ attW,
    const float* __restrict__ fcW, const float* __restrict__ fcb,
    const int* __restrict__ eidx, const float* __restrict__ target,
    float* __restrict__ out) {
    int b = blockIdx.x, t = threadIdx.x;

    // ---- phase 1: GCN layer 0 (128 blocks: 8 x-tiles x 16 ksplit) ----
    gcn_phase<0>(b & 7, b >> 3, t, gW1, gb1, eidx);
    if (b >= 64) return;

    // ---- phase 2: GCN layer 1 (64 blocks: 4 x-tiles x 16 ksplit) ----
    spin_flag(&g_flag1, t);
    gcn_phase<1>(b & 3, b >> 2, t, gW2, gb2, eidx);
    if (b >= 32) return;

    // ---- phase 3: ctx = m @ attW (32 blocks: 2 col x 16 ksplit) ----
    spin_flag(&g_flag2, t);
    {
        __shared__ float sm[32];
        int k0 = (b >> 1) * 32;
        if (t < 32) sm[t] = g_m[k0 + t];
        __syncthreads();
        int j = (b & 1) * 256 + t;
        float a = 0.f;
#pragma unroll
        for (int kb = 0; kb < 32; kb += 16) {
            float wv[16];
#pragma unroll
            for (int u = 0; u < 16; u++) wv[u] = __ldg(&attW[(size_t)(k0 + kb + u) * F2 + j]);
#pragma unroll
            for (int u = 0; u < 16; u++) a += sm[kb + u] * wv[u];
        }
        atomicAdd(&g_ctx[j], a);
        __threadfence();
        __syncthreads();
        if (t == 0) {
            if (atomicAdd(&g_done3, 1) == 31) atomicExch(&g_flag3, 1);
        }
    }
    if (b != 0) return;

    // ---- phase 4: attention pool + fc + softmax + loss ----
    spin_flag(&g_flag3, t);
    {
        __shared__ float ctx_s[F2];
        __shared__ float sc[N_NODES];
        __shared__ float lg[3];
        ctx_s[t]       = tanhf(g_ctx[t]);
        ctx_s[t + 256] = tanhf(g_ctx[t + 256]);
        if (t < 3) lg[t] = fcb[t];
        __syncthreads();

        int w = t >> 5, l = t & 31;
#pragma unroll
        for (int r = 0; r < 2; r++) {
            int n = w + 8 * r;
            if (n < N_NODES) {
                float v = 0.f;
#pragma unroll
                for (int q = 0; q < 16; q++) {
                    int j = l + 32 * q;
                    v += g_X2[n * F2 + j] * ctx_s[j];
                }
#pragma unroll
                for (int o = 16; o > 0; o >>= 1) v += __shfl_xor_sync(0xffffffffu, v, o);
                if (l == 0) sc[n] = 1.f / (1.f + expf(-v));
            }
        }
        __syncthreads();

        float p0 = 0.f, p1 = 0.f, p2 = 0.f;
#pragma unroll
        for (int r = 0; r < 2; r++) {
            int col = t + 256 * r;
            float rep = 0.f;
#pragma unroll
            for (int i = 0; i < N_NODES; i++) rep += g_X2[i * F2 + col] * sc[i];
            p0 += rep * fcW[col * 3 + 0];
            p1 += rep * fcW[col * 3 + 1];
            p2 += rep * fcW[col * 3 + 2];
        }
#pragma unroll
        for (int o = 16; o > 0; o >>= 1) {
            p0 += __shfl_xor_sync(0xffffffffu, p0, o);
            p1 += __shfl_xor_sync(0xffffffffu, p1, o);
            p2 += __shfl_xor_sync(0xffffffffu, p2, o);
        }
        if (l == 0) { atomicAdd(&lg[0], p0); atomicAdd(&lg[1], p1); atomicAdd(&lg[2], p2); }
        __syncthreads();

        if (t == 0) {
            float l0 = lg[0], l1 = lg[1], l2 = lg[2];
            float mx = fmaxf(l0, fmaxf(l1, l2));
            float e0 = expf(l0 - mx), e1 = expf(l1 - mx), e2 = expf(l2 - mx);
            float s = e0 + e1 + e2;
            float t0 = target[0], t1 = target[1], t2 = target[2];
            int cls = 0; float tm = t0;
            if (t1 > tm) { tm = t1; cls = 1; }
            if (t2 > tm) { tm = t2; cls = 2; }
            float lcls = (cls == 0) ? l0 : ((cls == 1) ? l1 : l2);
            out[0] = -(lcls - mx - logf(s));
            out[1] = e0 / s; out[2] = e1 / s; out[3] = e2 / s;
        }
    }
}

// ---------- host ----------
extern "C" void kernel_launch(void* const* d_in, const int* in_sizes, int n_in,
                              void* d_out, int out_size) {
    const float* f      = (const float*)d_in[0];
    const int*   eidx   = (const int*)  d_in[1];
    const float* target = (const float*)d_in[2];
    const float* W1     = (const float*)d_in[3];
    const float* b1     = (const float*)d_in[4];
    const float* W2     = (const float*)d_in[5];
    const float* b2     = (const float*)d_in[6];
    const float* W3     = (const float*)d_in[7];
    const float* b3     = (const float*)d_in[8];
    const float* gW1    = (const float*)d_in[9];
    const float* gb1    = (const float*)d_in[10];
    const float* gW2    = (const float*)d_in[11];
    const float* gb2    = (const float*)d_in[12];
    const float* attW   = (const float*)d_in[13];
    const float* fcW    = (const float*)d_in[14];
    const float* fcb    = (const float*)d_in[15];
    float* out = (float*)d_out;

    k_pre <<<148, 256>>>(f, W1, b1, W2, b2, b3);
    k_mlp3<<<dim3(60, 16), 128>>>((const float4*)W3);
    k_tail<<<128, 256>>>(gW1, gb1, gW2, gb2, attW, fcW, fcb, eidx, target, out);
}